// round 3
// baseline (speedup 1.0000x reference)
#include <cuda_runtime.h>

// Cubic B-spline (de Boor) elementwise evaluation, converted to piecewise
// power-basis polynomials. The clamped knot layout gives only a handful of
// valid intervals m in [k, nt-k-2]; each block symbolically runs de Boor once
// to build the cubic coefficients per interval, then the streaming loop is
// pure Horner + interval select -> memory bound.

#define KDEG 3
#define MAXM 16   // max number of polynomial pieces supported (nt <= 2*K+1+MAXM)

__global__ __launch_bounds__(256)
void bspline_eval_kernel(const float* __restrict__ in,
                         float* __restrict__ out,
                         const float* __restrict__ t,
                         const float* __restrict__ c,
                         int n, int nt)
{
    __shared__ float  s_thr[MAXM];     // interval thresholds t[k+1 .. nt-k-2]
    __shared__ float4 s_p[MAXM];       // power-basis coeffs per interval (p0,p1,p2,p3)

    const int numM = nt - 2 * KDEG - 1;   // number of intervals (m = KDEG + mi)

    // --- Per-block setup: symbolic de Boor -> polynomial coefficients ---
    // One lane per interval (numM is tiny: 3 for this problem).
    if (threadIdx.x < (unsigned)numM && threadIdx.x < MAXM) {
        const int mi = threadIdx.x;
        const int m  = KDEG + mi;

        // d[j] is a polynomial in x, degree grows with r. Coeff arrays are
        // statically indexed (fully unrolled) so they live in registers.
        float d[KDEG + 1][KDEG + 1];
        #pragma unroll
        for (int j = 0; j <= KDEG; ++j) {
            d[j][0] = c[m - KDEG + j];
            #pragma unroll
            for (int q = 1; q <= KDEG; ++q) d[j][q] = 0.0f;
        }

        #pragma unroll
        for (int r = 1; r <= KDEG; ++r) {
            #pragma unroll
            for (int j = KDEG; j >= 1; --j) {
                if (j < r) continue;
                const float left  = t[j + m - KDEG];
                const float right = t[j + 1 + m - r];
                const float denom = right - left;    // fp32, matches reference test
                if (denom > 0.0f) {
                    const float inv = 1.0f / denom;  // IEEE div, setup-only
                    const float a0  = -left * inv;
                    // d[j] = d[j-1] + (a0 + inv*x) * (d[j] - d[j-1])
                    float diff[KDEG + 1], nd[KDEG + 1];
                    #pragma unroll
                    for (int q = 0; q <= KDEG; ++q) {
                        diff[q] = d[j][q] - d[j - 1][q];
                        nd[q]   = fmaf(a0, diff[q], d[j - 1][q]);
                    }
                    #pragma unroll
                    for (int q = 0; q < KDEG; ++q)
                        nd[q + 1] = fmaf(inv, diff[q], nd[q + 1]);
                    #pragma unroll
                    for (int q = 0; q <= KDEG; ++q) d[j][q] = nd[q];
                } else {
                    #pragma unroll
                    for (int q = 0; q <= KDEG; ++q) d[j][q] = d[j - 1][q];
                }
            }
        }
        s_p[mi] = make_float4(d[KDEG][0], d[KDEG][1], d[KDEG][2], d[KDEG][3]);
        if (mi + 1 < numM) s_thr[mi] = t[KDEG + 1 + mi];
    }
    __syncthreads();

    const int nth = numM - 1;
    const int n4  = n >> 2;
    const float4* __restrict__ in4  = reinterpret_cast<const float4*>(in);
    float4* __restrict__       out4 = reinterpret_cast<float4*>(out);
    const int stride = blockDim.x * gridDim.x;

    // --- Streaming loop: float4 vectorized, grid-stride ---
    #pragma unroll 4
    for (int i = blockIdx.x * blockDim.x + threadIdx.x; i < n4; i += stride) {
        float4 v = in4[i];
        float xs[4] = {v.x, v.y, v.z, v.w};
        float ys[4];
        #pragma unroll
        for (int e = 0; e < 4; ++e) {
            const float x = xs[e];
            int mi = 0;
            for (int b = 0; b < nth; ++b) mi += (x >= s_thr[b]) ? 1 : 0;
            const float4 p = s_p[mi];
            float y = fmaf(fmaf(fmaf(p.w, x, p.z), x, p.y), x, p.x);
            ys[e] = (x == 0.0f) ? 0.0f : y;
        }
        out4[i] = make_float4(ys[0], ys[1], ys[2], ys[3]);
    }

    // --- Scalar tail (n not divisible by 4) ---
    for (int i = (n4 << 2) + blockIdx.x * blockDim.x + threadIdx.x; i < n;
         i += stride) {
        const float x = in[i];
        int mi = 0;
        for (int b = 0; b < nth; ++b) mi += (x >= s_thr[b]) ? 1 : 0;
        const float4 p = s_p[mi];
        float y = fmaf(fmaf(fmaf(p.w, x, p.z), x, p.y), x, p.x);
        out[i] = (x == 0.0f) ? 0.0f : y;
    }
}

extern "C" void kernel_launch(void* const* d_in, const int* in_sizes, int n_in,
                              void* d_out, int out_size)
{
    const float* imgs = (const float*)d_in[0];
    const float* t    = (const float*)d_in[1];
    const float* c    = (const float*)d_in[2];
    float* out        = (float*)d_out;

    const int n  = in_sizes[0];
    const int nt = in_sizes[1];

    const int threads = 256;
    // 8 blocks/SM * 148 SMs = 1184 -> 2048 threads/SM, grid-stride amortizes
    // the per-block polynomial setup over ~40 float4s per thread.
    int blocks = 1184;
    int needed = (n / 4 + threads - 1) / threads;
    if (needed < 1) needed = 1;
    if (blocks > needed) blocks = needed;

    bspline_eval_kernel<<<blocks, threads>>>(imgs, out, t, c, n, nt);
}

// round 4
// speedup vs baseline: 1.0590x; 1.0590x over previous
#include <cuda_runtime.h>

// Cubic B-spline (de Boor) elementwise evaluation via piecewise power-basis
// polynomials. For this problem's clamped knot layout nt=10 -> exactly 2
// cubic pieces split at one threshold, so the hot loop is register-only:
// evaluate both Horner cubics, select on x>=thr, zero-mask. Streaming
// float4 loads/stores with 4-deep load batching for MLP.

#define KDEG 3
#define MAXM 16

__global__ __launch_bounds__(256)
void bspline_eval_kernel(const float* __restrict__ in,
                         float* __restrict__ out,
                         const float* __restrict__ t,
                         const float* __restrict__ c,
                         int n, int nt)
{
    __shared__ float  s_thr[MAXM];
    __shared__ float4 s_p[MAXM];

    const int numM = nt - 2 * KDEG - 1;   // number of polynomial pieces

    // --- Per-block setup: symbolic de Boor -> power-basis coefficients ---
    if (threadIdx.x < (unsigned)numM && threadIdx.x < MAXM) {
        const int mi = threadIdx.x;
        const int m  = KDEG + mi;

        float d[KDEG + 1][KDEG + 1];
        #pragma unroll
        for (int j = 0; j <= KDEG; ++j) {
            d[j][0] = c[m - KDEG + j];
            #pragma unroll
            for (int q = 1; q <= KDEG; ++q) d[j][q] = 0.0f;
        }

        #pragma unroll
        for (int r = 1; r <= KDEG; ++r) {
            #pragma unroll
            for (int j = KDEG; j >= 1; --j) {
                if (j < r) continue;
                const float left  = t[j + m - KDEG];
                const float right = t[j + 1 + m - r];
                const float denom = right - left;
                if (denom > 0.0f) {
                    const float inv = 1.0f / denom;
                    const float a0  = -left * inv;
                    float diff[KDEG + 1], nd[KDEG + 1];
                    #pragma unroll
                    for (int q = 0; q <= KDEG; ++q) {
                        diff[q] = d[j][q] - d[j - 1][q];
                        nd[q]   = fmaf(a0, diff[q], d[j - 1][q]);
                    }
                    #pragma unroll
                    for (int q = 0; q < KDEG; ++q)
                        nd[q + 1] = fmaf(inv, diff[q], nd[q + 1]);
                    #pragma unroll
                    for (int q = 0; q <= KDEG; ++q) d[j][q] = nd[q];
                } else {
                    #pragma unroll
                    for (int q = 0; q <= KDEG; ++q) d[j][q] = d[j - 1][q];
                }
            }
        }
        s_p[mi] = make_float4(d[KDEG][0], d[KDEG][1], d[KDEG][2], d[KDEG][3]);
        if (mi + 1 < numM) s_thr[mi] = t[KDEG + 1 + mi];
    }
    __syncthreads();

    const int n4 = n >> 2;
    const float4* __restrict__ in4  = reinterpret_cast<const float4*>(in);
    float4* __restrict__       out4 = reinterpret_cast<float4*>(out);
    const int stride = blockDim.x * gridDim.x;
    int i = blockIdx.x * blockDim.x + threadIdx.x;

    if (numM == 2) {
        // ---- Fast path: two cubics, one threshold, all in registers ----
        const float4 pA = s_p[0];
        const float4 pB = s_p[1];
        const float  thr = s_thr[0];

        // Batched loop: 4 front-batched LDG.128 per iteration for MLP.
        for (; i + 3 * stride < n4; i += 4 * stride) {
            float4 v0 = __ldcs(in4 + i);
            float4 v1 = __ldcs(in4 + i + stride);
            float4 v2 = __ldcs(in4 + i + 2 * stride);
            float4 v3 = __ldcs(in4 + i + 3 * stride);
            float4 vv[4] = {v0, v1, v2, v3};
            float4 rr[4];
            #pragma unroll
            for (int b = 0; b < 4; ++b) {
                float xs[4] = {vv[b].x, vv[b].y, vv[b].z, vv[b].w};
                float ys[4];
                #pragma unroll
                for (int e = 0; e < 4; ++e) {
                    const float x  = xs[e];
                    const float yA = fmaf(fmaf(fmaf(pA.w, x, pA.z), x, pA.y), x, pA.x);
                    const float yB = fmaf(fmaf(fmaf(pB.w, x, pB.z), x, pB.y), x, pB.x);
                    float y = (x >= thr) ? yB : yA;
                    ys[e] = (x == 0.0f) ? 0.0f : y;
                }
                rr[b] = make_float4(ys[0], ys[1], ys[2], ys[3]);
            }
            __stcs(out4 + i,              rr[0]);
            __stcs(out4 + i + stride,     rr[1]);
            __stcs(out4 + i + 2 * stride, rr[2]);
            __stcs(out4 + i + 3 * stride, rr[3]);
        }
        // Remainder float4s
        for (; i < n4; i += stride) {
            float4 v = __ldcs(in4 + i);
            float xs[4] = {v.x, v.y, v.z, v.w};
            float ys[4];
            #pragma unroll
            for (int e = 0; e < 4; ++e) {
                const float x  = xs[e];
                const float yA = fmaf(fmaf(fmaf(pA.w, x, pA.z), x, pA.y), x, pA.x);
                const float yB = fmaf(fmaf(fmaf(pB.w, x, pB.z), x, pB.y), x, pB.x);
                float y = (x >= thr) ? yB : yA;
                ys[e] = (x == 0.0f) ? 0.0f : y;
            }
            __stcs(out4 + i, make_float4(ys[0], ys[1], ys[2], ys[3]));
        }
        // Scalar tail
        for (int s = (n4 << 2) + blockIdx.x * blockDim.x + threadIdx.x; s < n;
             s += stride) {
            const float x  = in[s];
            const float yA = fmaf(fmaf(fmaf(pA.w, x, pA.z), x, pA.y), x, pA.x);
            const float yB = fmaf(fmaf(fmaf(pB.w, x, pB.z), x, pB.y), x, pB.x);
            float y = (x >= thr) ? yB : yA;
            out[s] = (x == 0.0f) ? 0.0f : y;
        }
    } else {
        // ---- Generic path: smem threshold scan + coefficient lookup ----
        const int nth = numM - 1;
        for (; i < n4; i += stride) {
            float4 v = __ldcs(in4 + i);
            float xs[4] = {v.x, v.y, v.z, v.w};
            float ys[4];
            #pragma unroll
            for (int e = 0; e < 4; ++e) {
                const float x = xs[e];
                int mi = 0;
                for (int b = 0; b < nth; ++b) mi += (x >= s_thr[b]) ? 1 : 0;
                const float4 p = s_p[mi];
                float y = fmaf(fmaf(fmaf(p.w, x, p.z), x, p.y), x, p.x);
                ys[e] = (x == 0.0f) ? 0.0f : y;
            }
            __stcs(out4 + i, make_float4(ys[0], ys[1], ys[2], ys[3]));
        }
        for (int s = (n4 << 2) + blockIdx.x * blockDim.x + threadIdx.x; s < n;
             s += stride) {
            const float x = in[s];
            int mi = 0;
            for (int b = 0; b < nth; ++b) mi += (x >= s_thr[b]) ? 1 : 0;
            const float4 p = s_p[mi];
            float y = fmaf(fmaf(fmaf(p.w, x, p.z), x, p.y), x, p.x);
            out[s] = (x == 0.0f) ? 0.0f : y;
        }
    }
}

extern "C" void kernel_launch(void* const* d_in, const int* in_sizes, int n_in,
                              void* d_out, int out_size)
{
    const float* imgs = (const float*)d_in[0];
    const float* t    = (const float*)d_in[1];
    const float* c    = (const float*)d_in[2];
    float* out        = (float*)d_out;

    const int n  = in_sizes[0];
    const int nt = in_sizes[1];

    const int threads = 256;
    int blocks = 1184;                       // 8 blocks/SM on 148 SMs
    int needed = (n / 4 + threads - 1) / threads;
    if (needed < 1) needed = 1;
    if (blocks > needed) blocks = needed;

    bspline_eval_kernel<<<blocks, threads>>>(imgs, out, t, c, n, nt);
}